// round 9
// baseline (speedup 1.0000x reference)
#include <cuda_runtime.h>
#include <cuda_fp16.h>
#include <cstdint>
#include <cstddef>

#define NN     32768
#define KNB    16
#define FD     128
#define NEG    0.2f

// ---------------- device scratch ----------------
__device__ __align__(16) float g_U[2 * FD * FD];     // U[m][o][f] fp32
__device__ __align__(16) float g_nproj[NN * FD];     // nodes @ W^T + ba (folded)

// ---------------- smem layout for k_main ----------------
#define PB_BYTES  528        // B row pitch bytes: 264 fp16 (256 K + 8 pad)
#define SMEM_MAIN 67584      // 128 * 528 (B only — no A staging!)

// ---------------- helpers ----------------
__device__ __forceinline__ uint32_t smem_u32(const void* p) {
    uint32_t a;
    asm("{ .reg .u64 t; cvta.to.shared.u64 t, %1; cvt.u32.u64 %0, t; }" : "=r"(a) : "l"(p));
    return a;
}

__device__ __forceinline__ uint2 cvt4(float4 x) {
    __half2 a = __floats2half2_rn(x.x, x.y);
    __half2 b = __floats2half2_rn(x.z, x.w);
    uint2 r;
    r.x = *reinterpret_cast<uint32_t*>(&a);
    r.y = *reinterpret_cast<uint32_t*>(&b);
    return r;
}
__device__ __forceinline__ uint32_t cvt2(float2 x) {
    __half2 h = __floats2half2_rn(x.x, x.y);
    return *reinterpret_cast<uint32_t*>(&h);
}

#define LDSM4(r, addr) \
    asm volatile("ldmatrix.sync.aligned.m8n8.x4.shared.b16 {%0,%1,%2,%3}, [%4];" \
        : "=r"((r)[0]), "=r"((r)[1]), "=r"((r)[2]), "=r"((r)[3]) : "r"(addr))

#define MMA(d, a, b0_, b1_) \
    asm volatile("mma.sync.aligned.m16n8k16.row.col.f32.f16.f16.f32 " \
        "{%0,%1,%2,%3}, {%4,%5,%6,%7}, {%8,%9}, {%0,%1,%2,%3};" \
        : "+f"((d)[0]), "+f"((d)[1]), "+f"((d)[2]), "+f"((d)[3]) \
        : "r"((a)[0]), "r"((a)[1]), "r"((a)[2]), "r"((a)[3]), "r"(b0_), "r"(b1_))

// ---------------------------------------------------------------------------
// k_pre: merged.
//   blocks [0,16)   : U[m][o][f] = sum_op Wa[o][m*128+op] * W[op][f]   (fp32)
//   blocks [16,272) : nproj = fp16 HMMA nodes @ W^T + ba, 128 rows/block
// ---------------------------------------------------------------------------
#define NP_PITCH 272         // 136 fp16 per row (128 K + 8 pad)

__global__ __launch_bounds__(256, 2) void k_pre(const float* __restrict__ nodes,
                                                const float* __restrict__ W,
                                                const float* __restrict__ Wa,
                                                const float* __restrict__ ba) {
    extern __shared__ __align__(16) char smc[];
    const int tid = threadIdx.x;

    if (blockIdx.x < 16) {
        float* sW = reinterpret_cast<float*>(smc);          // [128][128]
        float* sT = reinterpret_cast<float*>(smc) + 16384;  // WaT [128 ops][16 rows]
        for (int i = tid; i < 16384; i += 256) sW[i] = __ldg(W + i);
        const int R0 = blockIdx.x * 16;
        for (int idx = tid; idx < 2048; idx += 256) {
            const int r = idx & 15, op = idx >> 4;
            const int R = R0 + r, m = R >> 7, o = R & 127;
            sT[op * 16 + r] = __ldg(Wa + o * 256 + m * 128 + op);
        }
        __syncthreads();
        const int f = tid & 127, rh = tid >> 7;
        float acc[8];
#pragma unroll
        for (int j = 0; j < 8; ++j) acc[j] = 0.f;
#pragma unroll 8
        for (int op = 0; op < 128; ++op) {
            const float w = sW[op * 128 + f];
            float4 wa0 = *reinterpret_cast<const float4*>(sT + op * 16 + rh * 8);
            float4 wa1 = *reinterpret_cast<const float4*>(sT + op * 16 + rh * 8 + 4);
            acc[0] += w * wa0.x; acc[1] += w * wa0.y; acc[2] += w * wa0.z; acc[3] += w * wa0.w;
            acc[4] += w * wa1.x; acc[5] += w * wa1.y; acc[6] += w * wa1.z; acc[7] += w * wa1.w;
        }
#pragma unroll
        for (int j = 0; j < 8; ++j)
            g_U[(R0 + rh * 8 + j) * 128 + f] = acc[j];
        return;
    }

    // ---- nproj via fp16 HMMA ----
    char* sB = smc;                  // W tile, row = out col o
    char* sA = smc + 34816;          // nodes tile
    const int lane = tid & 31, wid = tid >> 5;
    const int m0 = (wid >> 2) * 64, n0 = (wid & 3) * 32;
    const uint32_t smBase = smem_u32(smc);
    const int base = (blockIdx.x - 16) * 128;

    for (int i = tid; i < 4096; i += 256) {
        const int row = i >> 5, c4 = i & 31;
        float4 xb = __ldg(reinterpret_cast<const float4*>(W) + i);
        float4 xa = __ldg(reinterpret_cast<const float4*>(nodes + (size_t)(base + row) * FD) + c4);
        *reinterpret_cast<uint2*>(sB + row * NP_PITCH + c4 * 8) = cvt4(xb);
        *reinterpret_cast<uint2*>(sA + row * NP_PITCH + c4 * 8) = cvt4(xa);
    }
    __syncthreads();

    float acc[4][4][4];
#pragma unroll
    for (int mt = 0; mt < 4; ++mt)
#pragma unroll
        for (int nt = 0; nt < 4; ++nt)
#pragma unroll
            for (int i = 0; i < 4; ++i) acc[mt][nt][i] = 0.f;

    const int lane15 = lane & 15, laneHi = lane >> 4;
    const uint32_t aOff = smBase + 34816 + (m0 + lane15) * NP_PITCH + laneHi * 16;
    const uint32_t bOff = smBase + (n0 + lane15) * NP_PITCH + laneHi * 16;

#pragma unroll
    for (int ks = 0; ks < 8; ++ks) {
        const uint32_t ko = ks * 32;
        uint32_t ah[4][4], bh[2][4];
#pragma unroll
        for (int mt = 0; mt < 4; ++mt) LDSM4(ah[mt], aOff + mt * (16 * NP_PITCH) + ko);
        LDSM4(bh[0], bOff + ko);
        LDSM4(bh[1], bOff + 16 * NP_PITCH + ko);
#pragma unroll
        for (int mt = 0; mt < 4; ++mt)
#pragma unroll
            for (int nt = 0; nt < 4; ++nt) {
                const int g = nt >> 1, s = nt & 1;
                MMA(acc[mt][nt], ah[mt], bh[g][s], bh[g][2 + s]);
            }
    }

    const int q = lane & 3, r = lane >> 2;
#pragma unroll
    for (int mt = 0; mt < 4; ++mt) {
        const int row = base + m0 + mt * 16 + r;
#pragma unroll
        for (int nt = 0; nt < 4; ++nt) {
            const int col0 = n0 + nt * 8 + q * 2;
            const float b0 = __ldg(ba + col0), b1 = __ldg(ba + col0 + 1);
            float* a4 = acc[mt][nt];
            *reinterpret_cast<float2*>(g_nproj + (size_t)row * FD + col0)
                = make_float2(a4[0] + b0, a4[1] + b1);
            *reinterpret_cast<float2*>(g_nproj + (size_t)(row + 8) * FD + col0)
                = make_float2(a4[2] + b0, a4[3] + b1);
        }
    }
}

// ---------------------------------------------------------------------------
// Main: barrier-free persistent HMMA kernel.
// Warp tile = 16 edges (ONE node) x 128 out, K=256. A fragments loaded
// directly from gmem (LDG.64 per fragment register, prefetched 1 kt ahead,
// cross-node). B = fp16(U1|U2) resident in SMEM. No syncthreads in loop.
// ---------------------------------------------------------------------------
__global__ __launch_bounds__(256, 2) void k_main(
    const float* __restrict__ neighbors, const float* __restrict__ aspects,
    const float* __restrict__ att, const float* __restrict__ bias,
    float* __restrict__ out) {

    extern __shared__ __align__(16) char sm[];
    const int tid = threadIdx.x, lane = tid & 31, wid = tid >> 5;
    const uint32_t smBase = smem_u32(sm);

    // ---- build resident B = fp16(U1|U2), K-major row per output col ----
    for (int idx = tid; idx < 8192; idx += 256) {
        float4 x = __ldg(reinterpret_cast<const float4*>(g_U) + idx);
        uint2 h = cvt4(x);
        const int f4 = idx & 31, o = (idx >> 5) & 127, m = idx >> 12;
        *reinterpret_cast<uint2*>(sm + o * PB_BYTES + (m * 128 + f4 * 4) * 2) = h;
    }
    __syncthreads();   // only barrier in the kernel

    const int q = lane & 3, r = lane >> 2;
    const int lane15 = lane & 15, laneHi = lane >> 4;
    const uint32_t bBase = smBase + lane15 * PB_BYTES + laneHi * 16;

    float acc[16][4];
#pragma unroll
    for (int nt = 0; nt < 16; ++nt)
#pragma unroll
        for (int i = 0; i < 4; ++i) acc[nt][i] = 0.f;

    const int gw = blockIdx.x * 8 + wid;
    const int nw = gridDim.x * 8;
    const ptrdiff_t aspOff = aspects - neighbors;   // element offset

    int node = gw;
    // prefetch kt=0 of first node
    const float* c0 = neighbors + (size_t)(node * 16 + r) * FD + 2 * q;
    const float* c1 = c0 + 8 * FD;
    float2 p0 = __ldg(reinterpret_cast<const float2*>(c0));
    float2 p1 = __ldg(reinterpret_cast<const float2*>(c1));
    float2 p2 = __ldg(reinterpret_cast<const float2*>(c0 + 8));
    float2 p3 = __ldg(reinterpret_cast<const float2*>(c1 + 8));

#pragma unroll 1
    for (; node < NN; node += nw) {
        int nxt = node + nw; if (nxt >= NN) nxt = node;      // clamped safe prefetch
        const float* n0_ = neighbors + (size_t)(nxt * 16 + r) * FD + 2 * q;
        const float* n1_ = n0_ + 8 * FD;

#pragma unroll
        for (int kt = 0; kt < 16; ++kt) {
            // convert current prefetch to A fragments
            uint32_t af[4];
            af[0] = cvt2(p0); af[1] = cvt2(p1); af[2] = cvt2(p2); af[3] = cvt2(p3);
            // prefetch next kt (or next node's kt=0)
            {
                const int ktn = kt + 1;
                const float* b0;
                int col;
                if (ktn < 8)        { b0 = c0;           col = ktn * 16; }
                else if (ktn < 16)  { b0 = c0 + aspOff;  col = (ktn - 8) * 16; }
                else                { b0 = n0_;          col = 0; }
                const float* b1 = (ktn < 16) ? (b0 + 8 * FD) : n1_;
                p0 = __ldg(reinterpret_cast<const float2*>(b0 + col));
                p1 = __ldg(reinterpret_cast<const float2*>(b1 + col));
                p2 = __ldg(reinterpret_cast<const float2*>(b0 + col + 8));
                p3 = __ldg(reinterpret_cast<const float2*>(b1 + col + 8));
            }
            const uint32_t kb = (uint32_t)(kt * 32);
            // B fragments + MMA, in two halves (register pressure)
            uint32_t bh[4][4];
#pragma unroll
            for (int g = 0; g < 4; ++g) LDSM4(bh[g], bBase + g * (16 * PB_BYTES) + kb);
#pragma unroll
            for (int g = 0; g < 4; ++g) {
                MMA(acc[g * 2 + 0], af, bh[g][0], bh[g][2]);
                MMA(acc[g * 2 + 1], af, bh[g][1], bh[g][3]);
            }
#pragma unroll
            for (int g = 0; g < 4; ++g) LDSM4(bh[g], bBase + (g + 4) * (16 * PB_BYTES) + kb);
#pragma unroll
            for (int g = 0; g < 4; ++g) {
                MMA(acc[8 + g * 2 + 0], af, bh[g][0], bh[g][2]);
                MMA(acc[8 + g * 2 + 1], af, bh[g][1], bh[g][3]);
            }
        }
        // update row pointers for the node just prefetched
        c0 = n0_; c1 = n1_;

        // ---- epilogue (no barrier): this warp owns node entirely ----
        const int e0 = node * 16;
        const float attA = __ldg(att + e0 + r);
        const float attB = __ldg(att + e0 + 8 + r);
        const float* np = g_nproj + (size_t)node * FD;
#pragma unroll
        for (int nt = 0; nt < 16; ++nt) {
            const int col0 = nt * 8 + q * 2;
            const float nb0 = __ldg(np + col0);
            const float nb1 = __ldg(np + col0 + 1);
            float* a4 = acc[nt];
            float v0 = a4[0] + nb0, v1 = a4[1] + nb1;
            float v2 = a4[2] + nb0, v3 = a4[3] + nb1;
            v0 = fmaxf(v0, 0.f) + NEG * fminf(v0, 0.f);
            v1 = fmaxf(v1, 0.f) + NEG * fminf(v1, 0.f);
            v2 = fmaxf(v2, 0.f) + NEG * fminf(v2, 0.f);
            v3 = fmaxf(v3, 0.f) + NEG * fminf(v3, 0.f);
            float s0 = attA * __expf(v0) + attB * __expf(v2);
            float s1 = attA * __expf(v1) + attB * __expf(v3);
            s0 += __shfl_xor_sync(0xFFFFFFFFu, s0, 4);
            s1 += __shfl_xor_sync(0xFFFFFFFFu, s1, 4);
            s0 += __shfl_xor_sync(0xFFFFFFFFu, s0, 8);
            s1 += __shfl_xor_sync(0xFFFFFFFFu, s1, 8);
            s0 += __shfl_xor_sync(0xFFFFFFFFu, s0, 16);
            s1 += __shfl_xor_sync(0xFFFFFFFFu, s1, 16);
            if (r == 0) {
                float x0 = s0 + __ldg(bias + col0);
                float x1 = s1 + __ldg(bias + col0 + 1);
                float2 o2;
                o2.x = (x0 > 0.f) ? x0 : expm1f(x0);
                o2.y = (x1 > 0.f) ? x1 : expm1f(x1);
                *reinterpret_cast<float2*>(out + (size_t)node * FD + col0) = o2;
            }
            a4[0] = a4[1] = a4[2] = a4[3] = 0.f;
        }
    }
}

// ---------------------------------------------------------------------------
extern "C" void kernel_launch(void* const* d_in, const int* in_sizes, int n_in,
                              void* d_out, int out_size) {
    const float* nodes     = (const float*)d_in[0];
    const float* neighbors = (const float*)d_in[1];
    const float* aspects   = (const float*)d_in[2];
    const float* att       = (const float*)d_in[3];
    const float* W         = (const float*)d_in[4];
    const float* Wa        = (const float*)d_in[5];
    const float* ba        = (const float*)d_in[6];
    const float* bias      = (const float*)d_in[7];
    float* out = (float*)d_out;

    int dev = 0, nsm = 148;
    cudaGetDevice(&dev);
    cudaDeviceGetAttribute(&nsm, cudaDevAttrMultiProcessorCount, dev);

    const int smem_pre = 73728;   // max(preU 73728, nproj_h 69632)
    cudaFuncSetAttribute(k_pre,  cudaFuncAttributeMaxDynamicSharedMemorySize, smem_pre);
    cudaFuncSetAttribute(k_main, cudaFuncAttributeMaxDynamicSharedMemorySize, SMEM_MAIN);

    k_pre<<<272, 256, smem_pre>>>(nodes, W, Wa, ba);
    k_main<<<2 * nsm, 256, SMEM_MAIN>>>(neighbors, aspects, att, bias, out);
}

// round 16
// speedup vs baseline: 1.0261x; 1.0261x over previous
#include <cuda_runtime.h>
#include <cuda_fp16.h>
#include <cstdint>
#include <cstddef>

#define NN     32768
#define KNB    16
#define FD     128
#define NEG    0.2f
#define NTILES 8192          // 524288 edges / 64

// ---------------- device scratch ----------------
__device__ __align__(16) float g_U[2 * FD * FD];     // U[m][o][f] fp32
__device__ __align__(16) float g_nproj[NN * FD];     // nodes @ W^T + ba (folded)

// ---------------- smem layout for k_main (per CTA) ----------------
// B: 128 rows x 512 B (256 fp16 K), XOR-swizzled: col ^ ((row&31)<<4)
// A: 2-stage ring, 64 rows x 80 B (32 fp16 K + 16B pad)
#define SM_A      65536
#define A_STAGE   5120
#define SMEM_MAIN 75776      // 65536 + 2*5120

// ---------------- helpers ----------------
__device__ __forceinline__ uint32_t smem_u32(const void* p) {
    uint32_t a;
    asm("{ .reg .u64 t; cvta.to.shared.u64 t, %1; cvt.u32.u64 %0, t; }" : "=r"(a) : "l"(p));
    return a;
}
__device__ __forceinline__ uint2 cvt4(float4 x) {
    __half2 a = __floats2half2_rn(x.x, x.y);
    __half2 b = __floats2half2_rn(x.z, x.w);
    uint2 r;
    r.x = *reinterpret_cast<uint32_t*>(&a);
    r.y = *reinterpret_cast<uint32_t*>(&b);
    return r;
}

#define LDSM4(r, addr) \
    asm volatile("ldmatrix.sync.aligned.m8n8.x4.shared.b16 {%0,%1,%2,%3}, [%4];" \
        : "=r"((r)[0]), "=r"((r)[1]), "=r"((r)[2]), "=r"((r)[3]) : "r"(addr))

#define MMA(d, a, b0_, b1_) \
    asm volatile("mma.sync.aligned.m16n8k16.row.col.f32.f16.f16.f32 " \
        "{%0,%1,%2,%3}, {%4,%5,%6,%7}, {%8,%9}, {%0,%1,%2,%3};" \
        : "+f"((d)[0]), "+f"((d)[1]), "+f"((d)[2]), "+f"((d)[3]) \
        : "r"((a)[0]), "r"((a)[1]), "r"((a)[2]), "r"((a)[3]), "r"(b0_), "r"(b1_))

// ---------------------------------------------------------------------------
// k_pre (merged): blocks [0,16) U fp32; blocks [16,272) nproj fp16 HMMA + ba.
// ---------------------------------------------------------------------------
#define NP_PITCH 272

__global__ __launch_bounds__(256, 2) void k_pre(const float* __restrict__ nodes,
                                                const float* __restrict__ W,
                                                const float* __restrict__ Wa,
                                                const float* __restrict__ ba) {
    extern __shared__ __align__(16) char smc[];
    const int tid = threadIdx.x;

    if (blockIdx.x < 16) {
        float* sW = reinterpret_cast<float*>(smc);
        float* sT = reinterpret_cast<float*>(smc) + 16384;
        for (int i = tid; i < 16384; i += 256) sW[i] = __ldg(W + i);
        const int R0 = blockIdx.x * 16;
        for (int idx = tid; idx < 2048; idx += 256) {
            const int r = idx & 15, op = idx >> 4;
            const int R = R0 + r, m = R >> 7, o = R & 127;
            sT[op * 16 + r] = __ldg(Wa + o * 256 + m * 128 + op);
        }
        __syncthreads();
        const int f = tid & 127, rh = tid >> 7;
        float acc[8];
#pragma unroll
        for (int j = 0; j < 8; ++j) acc[j] = 0.f;
#pragma unroll 8
        for (int op = 0; op < 128; ++op) {
            const float w = sW[op * 128 + f];
            float4 wa0 = *reinterpret_cast<const float4*>(sT + op * 16 + rh * 8);
            float4 wa1 = *reinterpret_cast<const float4*>(sT + op * 16 + rh * 8 + 4);
            acc[0] += w * wa0.x; acc[1] += w * wa0.y; acc[2] += w * wa0.z; acc[3] += w * wa0.w;
            acc[4] += w * wa1.x; acc[5] += w * wa1.y; acc[6] += w * wa1.z; acc[7] += w * wa1.w;
        }
#pragma unroll
        for (int j = 0; j < 8; ++j)
            g_U[(R0 + rh * 8 + j) * 128 + f] = acc[j];
        return;
    }

    // ---- nproj via fp16 HMMA ----
    char* sB = smc;
    char* sA = smc + 34816;
    const int lane = tid & 31, wid = tid >> 5;
    const int m0 = (wid >> 2) * 64, n0 = (wid & 3) * 32;
    const uint32_t smBase = smem_u32(smc);
    const int base = (blockIdx.x - 16) * 128;

    for (int i = tid; i < 4096; i += 256) {
        const int row = i >> 5, c4 = i & 31;
        float4 xb = __ldg(reinterpret_cast<const float4*>(W) + i);
        float4 xa = __ldg(reinterpret_cast<const float4*>(nodes + (size_t)(base + row) * FD) + c4);
        *reinterpret_cast<uint2*>(sB + row * NP_PITCH + c4 * 8) = cvt4(xb);
        *reinterpret_cast<uint2*>(sA + row * NP_PITCH + c4 * 8) = cvt4(xa);
    }
    __syncthreads();

    float acc[4][4][4];
#pragma unroll
    for (int mt = 0; mt < 4; ++mt)
#pragma unroll
        for (int nt = 0; nt < 4; ++nt)
#pragma unroll
            for (int i = 0; i < 4; ++i) acc[mt][nt][i] = 0.f;

    const int lane15 = lane & 15, laneHi = lane >> 4;
    const uint32_t aOff = smBase + 34816 + (m0 + lane15) * NP_PITCH + laneHi * 16;
    const uint32_t bOff = smBase + (n0 + lane15) * NP_PITCH + laneHi * 16;

#pragma unroll
    for (int ks = 0; ks < 8; ++ks) {
        const uint32_t ko = ks * 32;
        uint32_t ah[4][4], bh[2][4];
#pragma unroll
        for (int mt = 0; mt < 4; ++mt) LDSM4(ah[mt], aOff + mt * (16 * NP_PITCH) + ko);
        LDSM4(bh[0], bOff + ko);
        LDSM4(bh[1], bOff + 16 * NP_PITCH + ko);
#pragma unroll
        for (int mt = 0; mt < 4; ++mt)
#pragma unroll
            for (int nt = 0; nt < 4; ++nt) {
                const int g = nt >> 1, s = nt & 1;
                MMA(acc[mt][nt], ah[mt], bh[g][s], bh[g][2 + s]);
            }
    }

    const int q = lane & 3, r = lane >> 2;
#pragma unroll
    for (int mt = 0; mt < 4; ++mt) {
        const int row = base + m0 + mt * 16 + r;
#pragma unroll
        for (int nt = 0; nt < 4; ++nt) {
            const int col0 = n0 + nt * 8 + q * 2;
            const float b0 = __ldg(ba + col0), b1 = __ldg(ba + col0 + 1);
            float* a4 = acc[mt][nt];
            *reinterpret_cast<float2*>(g_nproj + (size_t)row * FD + col0)
                = make_float2(a4[0] + b0, a4[1] + b1);
            *reinterpret_cast<float2*>(g_nproj + (size_t)(row + 8) * FD + col0)
                = make_float2(a4[2] + b0, a4[3] + b1);
        }
    }
}

// ---------------------------------------------------------------------------
// Main: persistent HMMA, tile = 64 edges x 128 out, K=256 (neigh|asp).
// 8 warps (2M x 4N), warp tile 32x32. K=32 chunks, 2-stage ring, 3 CTAs/SM.
// B unpadded 512B rows with XOR-16B swizzle (conflict-free LDSM).
// ---------------------------------------------------------------------------
__global__ __launch_bounds__(256, 3) void k_main(
    const float* __restrict__ neighbors, const float* __restrict__ aspects,
    const float* __restrict__ att, const float* __restrict__ bias,
    float* __restrict__ out) {

    extern __shared__ __align__(16) char sm[];
    const int tid = threadIdx.x, lane = tid & 31, wid = tid >> 5;
    const int m0 = (wid >> 2) * 32, n0 = (wid & 3) * 32;   // 2M x 4N  (FIXED)
    const uint32_t smBase = smem_u32(sm);

    // ---- build resident B = fp16(U1|U2), XOR-swizzled 512B rows ----
    for (int idx = tid; idx < 8192; idx += 256) {
        float4 x = __ldg(reinterpret_cast<const float4*>(g_U) + idx);
        uint2 h = cvt4(x);
        const int f4 = idx & 31, o = (idx >> 5) & 127, m = idx >> 12;
        const uint32_t col = (uint32_t)(m * 256 + f4 * 8);
        const uint32_t off = o * 512 + (col ^ (uint32_t)((o & 31) << 4));
        *reinterpret_cast<uint2*>(sm + off) = h;
    }
    __syncthreads();

    const int q = lane & 3, r = lane >> 2;
    const int lane15 = lane & 15, laneHi = lane >> 4;

    float acc[2][4][4];
#pragma unroll
    for (int mt = 0; mt < 2; ++mt)
#pragma unroll
        for (int nt = 0; nt < 4; ++nt)
#pragma unroll
            for (int i = 0; i < 4; ++i) acc[mt][nt][i] = 0.f;

    // A ldmatrix base (pitch 80)
    const uint32_t aRowOff = (uint32_t)((m0 + lane15) * 80 + laneHi * 16);
    const uint32_t aSt[2] = { smBase + SM_A + aRowOff, smBase + SM_A + A_STAGE + aRowOff };
    // B ldmatrix bases + per-lane XOR masks (row&31)<<4
    const uint32_t bRowA = smBase + (n0 + lane15) * 512;
    const uint32_t bRowB = smBase + (n0 + 16 + lane15) * 512;
    const uint32_t mskA  = (uint32_t)(((n0 + lane15) & 31) << 4);
    const uint32_t mskB  = (uint32_t)(((n0 + 16 + lane15) & 31) << 4);
    const uint32_t colHi = (uint32_t)(laneHi * 16);

    const int grid = gridDim.x;
    const int rowL = tid >> 2, sub = tid & 3;   // loader: 64 rows x 2 float4
    uint2 raw[2];
    int tile = blockIdx.x;
    if (tile < NTILES) {   // prologue: chunk 0 (neighbors, K cols 0..31)
        const float* src = neighbors + (size_t)tile * 8192 + rowL * 128 + sub * 4;
        raw[0] = cvt4(__ldg(reinterpret_cast<const float4*>(src)));
        raw[1] = cvt4(__ldg(reinterpret_cast<const float4*>(src + 16)));
    }

#pragma unroll 1
    for (; tile < NTILES; tile += grid) {
#pragma unroll
        for (int c = 0; c < 8; ++c) {
            const int stage = c & 1;
            // STS current chunk (already fp16), 64 rows x 32 K
            {
                char* aP = sm + SM_A + stage * A_STAGE + rowL * 80 + sub * 8;
                *reinterpret_cast<uint2*>(aP)      = raw[0];
                *reinterpret_cast<uint2*>(aP + 32) = raw[1];
            }
            __syncthreads();
            // prefetch next chunk (cvt to fp16 immediately)
            {
                int nc = c + 1, nt_ = tile;
                if (nc == 8) { nc = 0; nt_ = tile + grid; }
                if (nt_ < NTILES) {
                    const float* basep = (nc < 4) ? neighbors : aspects;
                    const float* src = basep + (size_t)nt_ * 8192 + (nc & 3) * 32
                                     + rowL * 128 + sub * 4;
                    raw[0] = cvt4(__ldg(reinterpret_cast<const float4*>(src)));
                    raw[1] = cvt4(__ldg(reinterpret_cast<const float4*>(src + 16)));
                }
            }
            // MMA on chunk c: 2 k-steps x (4 LDSM + 8 MMA)
            {
                const uint32_t aBase = aSt[stage];
                const uint32_t cByte = (uint32_t)(c * 64);
#pragma unroll
                for (int ks = 0; ks < 2; ++ks) {
                    const uint32_t ko  = (uint32_t)(ks * 32);
                    const uint32_t col = cByte + ko + colHi;
                    uint32_t ah[2][4], bh[2][4];
                    LDSM4(ah[0], aBase + ko);
                    LDSM4(ah[1], aBase + 16 * 80 + ko);
                    LDSM4(bh[0], bRowA + (col ^ mskA));
                    LDSM4(bh[1], bRowB + (col ^ mskB));
#pragma unroll
                    for (int mt = 0; mt < 2; ++mt)
#pragma unroll
                        for (int nt = 0; nt < 4; ++nt) {
                            const int g = nt >> 1, s = nt & 1;
                            MMA(acc[mt][nt], ah[mt], bh[g][s], bh[g][2 + s]);
                        }
                }
            }
        }

        // ---- epilogue: leaky->exp->att-weight, reduce 16 edges/node, elu, store ----
#pragma unroll
        for (int mt = 0; mt < 2; ++mt) {
            const int edge0 = tile * 64 + m0 + mt * 16;
            const float attA = __ldg(att + edge0 + r);
            const float attB = __ldg(att + edge0 + 8 + r);
            const int node = edge0 >> 4;
            const float* np = g_nproj + (size_t)node * FD;
#pragma unroll
            for (int nt = 0; nt < 4; ++nt) {
                const int col0 = n0 + nt * 8 + q * 2;
                const float nb0 = __ldg(np + col0);
                const float nb1 = __ldg(np + col0 + 1);
                float* a4 = acc[mt][nt];
                float v0 = a4[0] + nb0, v1 = a4[1] + nb1;
                float v2 = a4[2] + nb0, v3 = a4[3] + nb1;
                v0 = fmaxf(v0, 0.f) + NEG * fminf(v0, 0.f);
                v1 = fmaxf(v1, 0.f) + NEG * fminf(v1, 0.f);
                v2 = fmaxf(v2, 0.f) + NEG * fminf(v2, 0.f);
                v3 = fmaxf(v3, 0.f) + NEG * fminf(v3, 0.f);
                float s0 = attA * __expf(v0) + attB * __expf(v2);
                float s1 = attA * __expf(v1) + attB * __expf(v3);
                s0 += __shfl_xor_sync(0xFFFFFFFFu, s0, 4);
                s1 += __shfl_xor_sync(0xFFFFFFFFu, s1, 4);
                s0 += __shfl_xor_sync(0xFFFFFFFFu, s0, 8);
                s1 += __shfl_xor_sync(0xFFFFFFFFu, s1, 8);
                s0 += __shfl_xor_sync(0xFFFFFFFFu, s0, 16);
                s1 += __shfl_xor_sync(0xFFFFFFFFu, s1, 16);
                if (r == 0) {
                    float x0 = s0 + __ldg(bias + col0);
                    float x1 = s1 + __ldg(bias + col0 + 1);
                    float2 o2;
                    o2.x = (x0 > 0.f) ? x0 : expm1f(x0);
                    o2.y = (x1 > 0.f) ? x1 : expm1f(x1);
                    *reinterpret_cast<float2*>(out + (size_t)node * FD + col0) = o2;
                }
                a4[0] = a4[1] = a4[2] = a4[3] = 0.f;
            }
        }
    }
}

// ---------------------------------------------------------------------------
extern "C" void kernel_launch(void* const* d_in, const int* in_sizes, int n_in,
                              void* d_out, int out_size) {
    const float* nodes     = (const float*)d_in[0];
    const float* neighbors = (const float*)d_in[1];
    const float* aspects   = (const float*)d_in[2];
    const float* att       = (const float*)d_in[3];
    const float* W         = (const float*)d_in[4];
    const float* Wa        = (const float*)d_in[5];
    const float* ba        = (const float*)d_in[6];
    const float* bias      = (const float*)d_in[7];
    float* out = (float*)d_out;

    int dev = 0, nsm = 148;
    cudaGetDevice(&dev);
    cudaDeviceGetAttribute(&nsm, cudaDevAttrMultiProcessorCount, dev);

    const int smem_pre = 73728;
    cudaFuncSetAttribute(k_pre,  cudaFuncAttributeMaxDynamicSharedMemorySize, smem_pre);
    cudaFuncSetAttribute(k_main, cudaFuncAttributeMaxDynamicSharedMemorySize, SMEM_MAIN);

    k_pre<<<272, 256, smem_pre>>>(nodes, W, Wa, ba);
    k_main<<<3 * nsm, 256, SMEM_MAIN>>>(neighbors, aspects, att, bias, out);
}